// round 14
// baseline (speedup 1.0000x reference)
#include <cuda_runtime.h>
#include <cuda_bf16.h>
#include <cuda_fp16.h>
#include <stdint.h>
#include <math.h>

// ---------------- problem constants ----------------
#define BATCH 2
#define TSEQ 2048
#define BT (BATCH*TSEQ)          // 4096
#define DMODEL 2048
#define NHEADS 8
#define KVHEADS 4
#define GQA (NHEADS/KVHEADS)     // 2
#define HDIM 256
#define FFDIM 8192
#define WINDOW 1024
#define SOFTCAP 50.0f

typedef unsigned int u32;
typedef unsigned short u16;
typedef __nv_bfloat16 bf16;

// ---------------- scratch (no cudaMalloc allowed) ----------------
__device__ float g_q    [(size_t)BT*NHEADS*HDIM];
__device__ float g_kv   [(size_t)BT*2*KVHEADS*HDIM];
__device__ float g_aproj[(size_t)BT*DMODEL];
__device__ float g_ares [(size_t)BT*DMODEL];
__device__ float g_fout [(size_t)BT*DMODEL];

__device__ bf16 g_h_hi   [(size_t)BT*DMODEL];
__device__ bf16 g_h_lo   [(size_t)BT*DMODEL];
__device__ bf16 g_enc_hi [(size_t)BT*NHEADS*HDIM];
__device__ bf16 g_enc_lo [(size_t)BT*NHEADS*HDIM];
__device__ bf16 g_ffin_hi[(size_t)BT*DMODEL];
__device__ bf16 g_ffin_lo[(size_t)BT*DMODEL];
__device__ bf16 g_act_hi [(size_t)BT*FFDIM];
__device__ bf16 g_act_lo [(size_t)BT*FFDIM];

__device__ bf16 g_qp_hi[(size_t)BT*NHEADS*HDIM];
__device__ bf16 g_qp_lo[(size_t)BT*NHEADS*HDIM];
__device__ bf16 g_kp_hi[(size_t)BT*KVHEADS*HDIM];
__device__ bf16 g_kp_lo[(size_t)BT*KVHEADS*HDIM];
__device__ __half g_vp [(size_t)BT*KVHEADS*HDIM];

__device__ bf16 g_wq_hi [(size_t)NHEADS*HDIM*DMODEL];
__device__ bf16 g_wq_lo [(size_t)NHEADS*HDIM*DMODEL];
__device__ bf16 g_wkv_hi[(size_t)2*KVHEADS*HDIM*DMODEL];
__device__ bf16 g_wkv_lo[(size_t)2*KVHEADS*HDIM*DMODEL];
__device__ bf16 g_wav_hi[(size_t)DMODEL*NHEADS*HDIM];
__device__ bf16 g_wav_lo[(size_t)DMODEL*NHEADS*HDIM];
__device__ bf16 g_wg_hi [(size_t)2*FFDIM*DMODEL];      // interleaved: row r = (c=r&1, f=r>>1)
__device__ bf16 g_wg_lo [(size_t)2*FFDIM*DMODEL];
__device__ bf16 g_wl_hi [(size_t)DMODEL*FFDIM];
__device__ bf16 g_wl_lo [(size_t)DMODEL*FFDIM];

// ---------------- helpers ----------------
__device__ __forceinline__ void split_bf(float x, bf16& h, bf16& l){
    h = __float2bfloat16_rn(x);
    l = __float2bfloat16_rn(x - __bfloat162float(h));
}
__device__ __forceinline__ u32 pk(bf16 a, bf16 b){
    return (u32)__bfloat16_as_ushort(a) | ((u32)__bfloat16_as_ushort(b) << 16);
}
__device__ __forceinline__ u32 pkh(float a, float b){
    __half2 h = __floats2half2_rn(a, b);
    return *(u32*)&h;
}
__device__ __forceinline__ float gelu_f(float x){
    return 0.5f*x*(1.f + tanhf(0.7978845608028654f*(x + 0.044715f*x*x*x)));
}

// ---------------- row-wise RMSNorm (D=2048): f32 out and/or bf16 planes ----------------
__global__ void rows_norm_kernel(const float* __restrict__ in,
                                 const float* __restrict__ scale,
                                 const float* __restrict__ resid,
                                 const float* __restrict__ skip,
                                 float* __restrict__ outf,
                                 bf16* __restrict__ ohi,
                                 bf16* __restrict__ olo)
{
    const int row = blockIdx.x;
    const int tid = threadIdx.x;
    const size_t base = (size_t)row * DMODEL;
    float vals[8];
    float ss = 0.f;
#pragma unroll
    for (int i = 0; i < 8; i++) {
        float v = in[base + tid + i*256];
        vals[i] = v; ss += v*v;
    }
    __shared__ float red[8];
#pragma unroll
    for (int o = 16; o; o >>= 1) ss += __shfl_xor_sync(0xffffffffu, ss, o);
    if ((tid & 31) == 0) red[tid >> 5] = ss;
    __syncthreads();
    if (tid < 32) {
        float t = (tid < 8) ? red[tid] : 0.f;
#pragma unroll
        for (int o = 4; o; o >>= 1) t += __shfl_xor_sync(0xffffffffu, t, o);
        if (tid == 0) red[0] = t;
    }
    __syncthreads();
    const float inv = rsqrtf(red[0] * (1.f/DMODEL) + 1e-6f);
    const float sk = skip ? skip[0] : 1.f;
#pragma unroll
    for (int i = 0; i < 8; i++) {
        const int d = tid + i*256;
        float o = vals[i] * inv * (1.f + (scale ? scale[d] : 0.f));
        if (resid) o += resid[base + d] * sk;
        if (outf) outf[base + d] = o;
        if (ohi) { bf16 h,l; split_bf(o,h,l); ohi[base+d]=h; olo[base+d]=l; }
    }
}

// ---------------- weight conversion kernels ----------------
__global__ void split_kernel(const float* __restrict__ src,
                             bf16* __restrict__ hi, bf16* __restrict__ lo, int n4)
{
    const int i = blockIdx.x * blockDim.x + threadIdx.x;
    if (i >= n4) return;
    float4 v = ((const float4*)src)[i];
    bf16 h0,l0,h1,l1,h2,l2,h3,l3;
    split_bf(v.x,h0,l0); split_bf(v.y,h1,l1);
    split_bf(v.z,h2,l2); split_bf(v.w,h3,l3);
    ((uint2*)hi)[i] = make_uint2(pk(h0,h1), pk(h2,h3));
    ((uint2*)lo)[i] = make_uint2(pk(l0,l1), pk(l2,l3));
}

// w_gating [2][F][D] -> interleaved rows: dst row r = src (c=r&1, f=r>>1)
__global__ void interleave_split_kernel(const float* __restrict__ src,
                                        bf16* __restrict__ hi, bf16* __restrict__ lo,
                                        int n4)
{
    const int i = blockIdx.x * blockDim.x + threadIdx.x;
    if (i >= n4) return;
    const int per_row = DMODEL/4;
    const int r = i / per_row, c4 = (i % per_row);
    const size_t s = ((size_t)(r & 1)*FFDIM + (r >> 1))*(DMODEL/4) + c4;
    float4 v = ((const float4*)src)[s];
    bf16 h0,l0,h1,l1,h2,l2,h3,l3;
    split_bf(v.x,h0,l0); split_bf(v.y,h1,l1);
    split_bf(v.z,h2,l2); split_bf(v.w,h3,l3);
    ((uint2*)hi)[i] = make_uint2(pk(h0,h1), pk(h2,h3));
    ((uint2*)lo)[i] = make_uint2(pk(l0,l1), pk(l2,l3));
}

__global__ void trans_split_kernel(const float* __restrict__ src,
                                   bf16* __restrict__ hi, bf16* __restrict__ lo,
                                   int R, int C, size_t src_zstride,
                                   int dstrow0, int dstrow_z, int dld)
{
    src += (size_t)blockIdx.z * src_zstride;
    const int r0 = blockIdx.y * 32, c0 = blockIdx.x * 32;
    __shared__ float t[32][33];
    const int tx = threadIdx.x & 31, ty = threadIdx.x >> 5;
#pragma unroll
    for (int i = 0; i < 4; i++) {
        const int r = r0 + ty + i*8;
        t[ty + i*8][tx] = src[(size_t)r*C + c0 + tx];
    }
    __syncthreads();
    const int drow0 = dstrow0 + blockIdx.z * dstrow_z;
#pragma unroll
    for (int i = 0; i < 4; i++) {
        const int c = c0 + ty + i*8;
        const int r = r0 + tx;
        const float v = t[tx][ty + i*8];
        bf16 h,l; split_bf(v,h,l);
        const size_t o = (size_t)(drow0 + c)*dld + r;
        hi[o] = h; lo[o] = l;
    }
}

// ---------------- common asm macros ----------------
#define MMABF(d, a, b)                                                            \
    asm volatile("mma.sync.aligned.m16n8k16.row.col.f32.bf16.bf16.f32 "           \
        "{%0,%1,%2,%3}, {%4,%5,%6,%7}, {%8,%9}, {%0,%1,%2,%3};"                   \
        : "+f"(d[0]), "+f"(d[1]), "+f"(d[2]), "+f"(d[3])                          \
        : "r"(a[0]), "r"(a[1]), "r"(a[2]), "r"(a[3]), "r"(b[0]), "r"(b[1]));
#define MMAFP(d, a, b0_, b1_)                                                     \
    asm volatile("mma.sync.aligned.m16n8k16.row.col.f32.f16.f16.f32 "             \
        "{%0,%1,%2,%3}, {%4,%5,%6,%7}, {%8,%9}, {%0,%1,%2,%3};"                   \
        : "+f"(d[0]), "+f"(d[1]), "+f"(d[2]), "+f"(d[3])                          \
        : "r"(a[0]), "r"(a[1]), "r"(a[2]), "r"(a[3]), "r"(b0_), "r"(b1_));
#define LDM4(r0,r1,r2,r3,a)                                                       \
    asm volatile("ldmatrix.sync.aligned.m8n8.x4.shared.b16 {%0,%1,%2,%3}, [%4];"  \
        : "=r"(r0), "=r"(r1), "=r"(r2), "=r"(r3) : "r"(a));
#define LDM4T(r0,r1,r2,r3,a)                                                      \
    asm volatile("ldmatrix.sync.aligned.m8n8.x4.trans.shared.b16 {%0,%1,%2,%3}, [%4];" \
        : "=r"(r0), "=r"(r1), "=r"(r2), "=r"(r3) : "r"(a));
#define CPA(dst, src)                                                             \
    asm volatile("cp.async.cg.shared.global [%0], [%1], 16;" :: "r"(dst), "l"(src))

// ------------- bf16 split-3 NT GEMM, pre-split planes, 3-stage cp.async -------------
// A planes [M][K], B planes [N][K]. EPI=0: C f32 [M][ldc]. EPI=1: gated-gelu epilogue
// writing act planes ahi/alo [M][ldc/2] (B rows interleaved gate0/gate1).
#define GSM_BUF 8192                      // u32 per buffer (32KB)
#define GSM3_TOTAL (3*GSM_BUF*4)          // 96KB

template<int EPI>
__global__ __launch_bounds__(256, 2)
void gemm_planes_nt(const bf16* __restrict__ Ah, const bf16* __restrict__ Al,
                    const bf16* __restrict__ Bh, const bf16* __restrict__ Bl,
                    float* __restrict__ C, bf16* __restrict__ ahi,
                    bf16* __restrict__ alo, int K, int ldc)
{
    extern __shared__ u32 smemu[];
    const u32 sbase = (u32)__cvta_generic_to_shared(smemu);

    const int tid  = threadIdx.x;
    const int lane = tid & 31;
    const int warp = tid >> 5;
    const int wm = (warp >> 2) * 64;
    const int wn = (warp & 3) * 32;
    const int qr = lane >> 2, qc = lane & 3;
    const int m0 = blockIdx.y * 128, n0 = blockIdx.x * 128;

    float acc[4][4][4];
#pragma unroll
    for (int i = 0; i < 4; i++)
#pragma unroll
        for (int j = 0; j < 4; j++) {
            acc[i][j][0]=0.f; acc[i][j][1]=0.f; acc[i][j][2]=0.f; acc[i][j][3]=0.f;
        }

    auto stage = [&](int k0, int buf) {
#pragma unroll
        for (int i = 0; i < 8; i++) {
            const int id = tid + i*256;
            const int plane = id >> 9;
            const int wi = id & 511;
            const int row = wi >> 2, g = wi & 3;
            const bf16* sp;
            if      (plane == 0) sp = Ah + (size_t)(m0 + row)*K;
            else if (plane == 1) sp = Al + (size_t)(m0 + row)*K;
            else if (plane == 2) sp = Bh + (size_t)(n0 + row)*K;
            else                 sp = Bl + (size_t)(n0 + row)*K;
            const u32 dst = sbase + (buf*GSM_BUF + plane*2048 + row*16 +
                                     ((g ^ ((row & 7) >> 1)) << 2)) * 4;
            CPA(dst, sp + k0 + g*8);
        }
        asm volatile("cp.async.commit_group;");
    };

    const int nIt = K / 32;                // >= 2 always here
    stage(0, 0);
    stage(32, 1);

    for (int it = 0; it < nIt; it++) {
        const int cur = it % 3;
        if (it + 1 < nIt) asm volatile("cp.async.wait_group 1;");
        else              asm volatile("cp.async.wait_group 0;");
        __syncthreads();
        if (it + 2 < nIt) stage((it + 2) * 32, (it + 2) % 3);

        const u32 abase = sbase + (cur*GSM_BUF)*4;
        const int b = lane & 7, t = lane >> 3;
#pragma unroll
        for (int ks = 0; ks < 2; ks++) {
            u32 bh[4][2], bl[4][2];
#pragma unroll
            for (int np = 0; np < 2; np++) {
                const int row = wn + np*16 + ((t & 2) << 2) + b;
                const int g = 2*ks + (t & 1);
                const u32 off = (row*16 + ((g ^ (b >> 1)) << 2)) * 4;
                u32 r0,r1,r2,r3;
                LDM4(r0,r1,r2,r3, abase + 4096*4 + off);
                bh[2*np][0]=r0; bh[2*np][1]=r1; bh[2*np+1][0]=r2; bh[2*np+1][1]=r3;
                LDM4(r0,r1,r2,r3, abase + 6144*4 + off);
                bl[2*np][0]=r0; bl[2*np][1]=r1; bl[2*np+1][0]=r2; bl[2*np+1][1]=r3;
            }
#pragma unroll
            for (int mf = 0; mf < 4; mf++) {
                const int row = wm + mf*16 + ((t & 1) << 3) + b;
                const int g = 2*ks + (t >> 1);
                const u32 off = (row*16 + ((g ^ (b >> 1)) << 2)) * 4;
                u32 ah[4], al[4];
                LDM4(ah[0],ah[1],ah[2],ah[3], abase + off);
                LDM4(al[0],al[1],al[2],al[3], abase + 2048*4 + off);
#pragma unroll
                for (int nf = 0; nf < 4; nf++) {
                    MMABF(acc[mf][nf], ah, bh[nf]);
                    MMABF(acc[mf][nf], ah, bl[nf]);
                    MMABF(acc[mf][nf], al, bh[nf]);
                }
            }
        }
        __syncthreads();   // all reads of buffer cur done before it is restaged (it+3)
    }

    if (EPI == 0) {
#pragma unroll
        for (int mf = 0; mf < 4; mf++) {
            const int r = m0 + wm + mf*16 + qr;
#pragma unroll
            for (int nf = 0; nf < 4; nf++) {
                const int c = n0 + wn + nf*8 + 2*qc;
                *(float2*)(C + (size_t)r*ldc + c)     = make_float2(acc[mf][nf][0], acc[mf][nf][1]);
                *(float2*)(C + (size_t)(r+8)*ldc + c) = make_float2(acc[mf][nf][2], acc[mf][nf][3]);
            }
        }
    } else {
        // interleaved gating: acc[..][0]=gate0, acc[..][1]=gate1 for f = col/2
        const int fld = ldc >> 1;
#pragma unroll
        for (int mf = 0; mf < 4; mf++) {
            const int r = m0 + wm + mf*16 + qr;
#pragma unroll
            for (int nf = 0; nf < 4; nf++) {
                const int f = (n0 + wn + nf*8 + 2*qc) >> 1;
                const float a0 = gelu_f(acc[mf][nf][0]) * acc[mf][nf][1];
                const float a1 = gelu_f(acc[mf][nf][2]) * acc[mf][nf][3];
                bf16 h,l;
                split_bf(a0,h,l);
                ahi[(size_t)r*fld + f] = h; alo[(size_t)r*fld + f] = l;
                split_bf(a1,h,l);
                ahi[(size_t)(r+8)*fld + f] = h; alo[(size_t)(r+8)*fld + f] = l;
            }
        }
    }
}

// ---------------- per-head RMSNorm + RoPE (H=256) -> split planes ----------------
__global__ void qkv_post_kernel(const float* __restrict__ buf, int ld,
                                const float* __restrict__ nscale,
                                const int* __restrict__ segpos,
                                int dorope,
                                bf16* __restrict__ ohi, bf16* __restrict__ olo,
                                __half* __restrict__ ovh, int pld)
{
    const int bt = blockIdx.x;
    const int head = blockIdx.y;
    const int h = threadIdx.x;
    const float* p = buf + (size_t)bt * ld + head * HDIM;
    float v = p[h];
    __shared__ float red[8];
    __shared__ float nb[HDIM];
    float ss = v * v;
#pragma unroll
    for (int o = 16; o; o >>= 1) ss += __shfl_xor_sync(0xffffffffu, ss, o);
    if ((h & 31) == 0) red[h >> 5] = ss;
    __syncthreads();
    if (h < 32) {
        float t = (h < 8) ? red[h] : 0.f;
#pragma unroll
        for (int o = 4; o; o >>= 1) t += __shfl_xor_sync(0xffffffffu, t, o);
        if (h == 0) red[0] = t;
    }
    __syncthreads();
    float normed = v * rsqrtf(red[0] * (1.f/HDIM) + 1e-6f);
    if (nscale) normed *= (1.f + nscale[h]);
    if (dorope) {
        nb[h] = normed;
        __syncthreads();
        const int i = h & 127;
        const float ts = exp2f((float)i * (13.287712379549449f / 128.f));
        const float ang = (float)segpos[bt] / ts;
        float sn, cs;
        sincosf(ang, &sn, &cs);
        const float fi = nb[i], se = nb[i + 128];
        normed = (h < 128) ? (fi*cs - se*sn) : (se*cs + fi*sn);
    }
    const size_t o = (size_t)bt*pld + head*HDIM + h;
    if (ohi) { bf16 hh,ll; split_bf(normed,hh,ll); ohi[o]=hh; olo[o]=ll; }
    if (ovh) ovh[o] = __float2half(normed);
}

// ---------------- tensor-core flash attention (R10, unchanged) ----------------
#define ATT_QH   0
#define ATT_QL   65536
#define ATT_KV0  131072
#define ATT_KVSZ 49152
#define ATT_PTS  229376
#define ATT_PSS  229888
#define ATT_SMEM 230144

__global__ __launch_bounds__(256, 1)
void attn_tc_kernel(const bf16* __restrict__ qph, const bf16* __restrict__ qpl,
                    const bf16* __restrict__ kph, const bf16* __restrict__ kpl,
                    const __half* __restrict__ vp, const int* __restrict__ segpos,
                    bf16* __restrict__ ehi, bf16* __restrict__ elo)
{
    extern __shared__ char smb[];
    const u32 sb = (u32)__cvta_generic_to_shared(smb);
    int* ptsm = (int*)(smb + ATT_PTS);
    int* pssm = (int*)(smb + ATT_PSS);

    const int b = blockIdx.z, n = blockIdx.y, tile = blockIdx.x;
    const int t0 = tile * 128;
    const int kk = n / GQA;
    const int tid = threadIdx.x, lane = tid & 31, warp = tid >> 5;
    const int qr = lane >> 2, qc = lane & 3;
    const int tq0 = t0 + warp*16;
    const int rl = lane & 7, tl = lane >> 3;

    {
        const size_t qbase = ((size_t)(b*TSEQ + t0))*(NHEADS*HDIM) + n*HDIM;
#pragma unroll
        for (int i = 0; i < 16; i++) {
            const int id = tid + i*256;
            const int row = id >> 5, g = id & 31;
            const u32 dst = sb + row*512 + ((g ^ (row & 7)) << 4);
            const size_t off = qbase + (size_t)row*(NHEADS*HDIM) + g*8;
            CPA(dst, qph + off);
            CPA(dst + ATT_QL, qpl + off);
        }
        if (tid < 128) ptsm[tid] = segpos[b*TSEQ + t0 + tid];
    }
    asm volatile("cp.async.commit_group;");

    int s_begin = t0 - (WINDOW - 1); if (s_begin < 0) s_begin = 0;
    s_begin &= ~31;
    const int nch = (t0 + 128 - s_begin) >> 5;

    auto stageKV = [&](int s0, int buf) {
        const size_t kb = ((size_t)(b*TSEQ + s0))*(KVHEADS*HDIM) + kk*HDIM;
#pragma unroll
        for (int i = 0; i < 4; i++) {
            const int id = tid + i*256;
            const int row = id >> 5, g = id & 31;
            const u32 dst = sb + ATT_KV0 + buf*ATT_KVSZ + row*512 + ((g ^ (row & 7)) << 4);
            const size_t off = kb + (size_t)row*(KVHEADS*HDIM) + g*8;
            CPA(dst,         kph + off);
            CPA(dst + 16384, kpl + off);
            CPA(dst + 32768, vp  + off);
        }
        if (tid < 32) pssm[buf*32 + tid] = segpos[b*TSEQ + s0 + tid];
        asm volatile("cp.async.commit_group;");
    };

    stageKV(s_begin, 0);

    float acc[32][4];
#pragma unroll
    for (int j = 0; j < 32; j++) { acc[j][0]=0.f; acc[j][1]=0.f; acc[j][2]=0.f; acc[j][3]=0.f; }
    float mprev0 = -1e30f, mprev1 = -1e30f, l0 = 0.f, l1 = 0.f;

    for (int c = 0; c < nch; c++) {
        const int s0 = s_begin + c*32;
        const int cur = c & 1;
        const bool more = (c + 1 < nch);
        if (more) stageKV(s0 + 32, cur ^ 1);
        if (more) asm volatile("cp.async.wait_group 1;");
        else      asm volatile("cp.async.wait_group 0;");
        __syncthreads();

        const bool active = !(s0 > tq0 + 15 || s0 + 31 < tq0 - (WINDOW - 1));
        if (active) {
            const u32 kvb = sb + ATT_KV0 + cur*ATT_KVSZ;
            float S[4][4];
#pragma unroll
            for (int j = 0; j < 4; j++) { S[j][0]=0.f; S[j][1]=0.f; S[j][2]=0.f; S[j][3]=0.f; }
#pragma unroll
            for (int t = 0; t < 16; t++) {
                u32 aqh[4], aql[4];
                {
                    const int row = warp*16 + rl + ((tl & 1) << 3);
                    const int g = 2*t + (tl >> 1);
                    const u32 addr = sb + row*512 + ((g ^ (row & 7)) << 4);
                    LDM4(aqh[0],aqh[1],aqh[2],aqh[3], addr);
                    LDM4(aql[0],aql[1],aql[2],aql[3], addr + ATT_QL);
                }
                u32 bh[4][2], bl[4][2];
#pragma unroll
                for (int p2 = 0; p2 < 2; p2++) {
                    const int row = p2*16 + ((tl >> 1) << 3) + rl;
                    const int g = 2*t + (tl & 1);
                    const u32 addr = kvb + row*512 + ((g ^ (row & 7)) << 4);
                    u32 r0,r1,r2,r3;
                    LDM4(r0,r1,r2,r3, addr);
                    bh[2*p2][0]=r0; bh[2*p2][1]=r1; bh[2*p2+1][0]=r2; bh[2*p2+1][1]=r3;
                    LDM4(r0,r1,r2,r3, addr + 16384);
                    bl[2*p2][0]=r0; bl[2*p2][1]=r1; bl[2*p2+1][0]=r2; bl[2*p2+1][1]=r3;
                }
#pragma unroll
                for (int j = 0; j < 4; j++) {
                    MMABF(S[j], aqh, bh[j]);
                    MMABF(S[j], aqh, bl[j]);
                    MMABF(S[j], aql, bh[j]);
                }
            }
            const int pt0 = ptsm[warp*16 + qr], pt1 = ptsm[warp*16 + qr + 8];
            const int tg0 = tq0 + qr, tg1 = tq0 + qr + 8;
#pragma unroll
            for (int j = 0; j < 4; j++) {
#pragma unroll
                for (int e = 0; e < 2; e++) {
                    const int scol = s0 + j*8 + 2*qc + e;
                    const int ps = pssm[cur*32 + j*8 + 2*qc + e];
                    float v0 = tanhf(S[j][e] * (1.f/SOFTCAP)) * SOFTCAP;
                    S[j][e] = ((scol <= tg0) && (ps > pt0 - WINDOW) && (ps < pt0 + WINDOW))
                              ? v0 : -1e30f;
                    float v1 = tanhf(S[j][2+e] * (1.f/SOFTCAP)) * SOFTCAP;
                    S[j][2+e] = ((scol <= tg1) && (ps > pt1 - WINDOW) && (ps < pt1 + WINDOW))
                              ? v1 : -1e30f;
                }
            }
            float m0 = -1e30f, m1 = -1e30f;
#pragma unroll
            for (int j = 0; j < 4; j++) {
                m0 = fmaxf(m0, fmaxf(S[j][0], S[j][1]));
                m1 = fmaxf(m1, fmaxf(S[j][2], S[j][3]));
            }
            m0 = fmaxf(m0, __shfl_xor_sync(0xffffffffu, m0, 1));
            m0 = fmaxf(m0, __shfl_xor_sync(0xffffffffu, m0, 2));
            m1 = fmaxf(m1, __shfl_xor_sync(0xffffffffu, m1, 1));
            m1 = fmaxf(m1, __shfl_xor_sync(0xffffffffu, m1, 2));
            const float mn0 = fmaxf(mprev0, m0), mn1 = fmaxf(mprev1, m1);
            const float sc0 = __expf(mprev0 - mn0), sc1 = __expf(mprev1 - mn1);
            mprev0 = mn0; mprev1 = mn1;
            float ps0 = 0.f, ps1 = 0.f;
#pragma unroll
            for (int j = 0; j < 4; j++) {
                S[j][0] = __expf(S[j][0] - mn0); S[j][1] = __expf(S[j][1] - mn0);
                S[j][2] = __expf(S[j][2] - mn1); S[j][3] = __expf(S[j][3] - mn1);
                ps0 += S[j][0] + S[j][1];
                ps1 += S[j][2] + S[j][3];
            }
            ps0 += __shfl_xor_sync(0xffffffffu, ps0, 1);
            ps0 += __shfl_xor_sync(0xffffffffu, ps0, 2);
            ps1 += __shfl_xor_sync(0xffffffffu, ps1, 1);
            ps1 += __shfl_xor_sync(0xffffffffu, ps1, 2);
            l0 = l0*sc0 + ps0; l1 = l1*sc1 + ps1;
#pragma unroll
            for (int j = 0; j < 32; j++) {
                acc[j][0] *= sc0; acc[j][1] *= sc0;
                acc[j][2] *= sc1; acc[j][3] *= sc1;
            }
            u32 P[2][4];
#pragma unroll
            for (int ks = 0; ks < 2; ks++) {
                P[ks][0] = pkh(S[2*ks][0],   S[2*ks][1]);
                P[ks][1] = pkh(S[2*ks][2],   S[2*ks][3]);
                P[ks][2] = pkh(S[2*ks+1][0], S[2*ks+1][1]);
                P[ks][3] = pkh(S[2*ks+1][2], S[2*ks+1][3]);
            }
#pragma unroll
            for (int ks = 0; ks < 2; ks++) {
#pragma unroll
                for (int jj = 0; jj < 16; jj++) {
                    const int row = ks*16 + ((tl & 1) << 3) + rl;
                    const int g = 2*jj + (tl >> 1);
                    const u32 addr = kvb + 32768 + row*512 + ((g ^ (row & 7)) << 4);
                    u32 r0,r1,r2,r3;
                    LDM4T(r0,r1,r2,r3, addr);
                    MMAFP(acc[2*jj],   P[ks], r0, r1);
                    MMAFP(acc[2*jj+1], P[ks], r2, r3);
                }
            }
        }
        __syncthreads();
    }

    const float inv0 = 1.f / l0, inv1 = 1.f / l1;
    const size_t r0b = ((size_t)(b*TSEQ + tq0 + qr))*(NHEADS*HDIM);
    const size_t r1b = ((size_t)(b*TSEQ + tq0 + qr + 8))*(NHEADS*HDIM);
#pragma unroll
    for (int j = 0; j < 32; j++) {
        const int col = n*HDIM + j*8 + 2*qc;
        float o0 = acc[j][0]*inv0, o1 = acc[j][1]*inv0;
        float o2 = acc[j][2]*inv1, o3 = acc[j][3]*inv1;
        bf16 h0,l0b,h1,l1b,h2,l2b,h3,l3b;
        split_bf(o0,h0,l0b); split_bf(o1,h1,l1b);
        split_bf(o2,h2,l2b); split_bf(o3,h3,l3b);
        *(u32*)(ehi + r0b + col) = pk(h0,h1);
        *(u32*)(elo + r0b + col) = pk(l0b,l1b);
        *(u32*)(ehi + r1b + col) = pk(h2,h3);
        *(u32*)(elo + r1b + col) = pk(l2b,l3b);
    }
}

// ---------------- launch ----------------
template<typename T>
static T* symaddr(const void* sym) {
    void* p = nullptr;
    cudaGetSymbolAddress(&p, sym);
    return (T*)p;
}

extern "C" void kernel_launch(void* const* d_in, const int* in_sizes, int n_in,
                              void* d_out, int out_size)
{
    const float* x        = (const float*)d_in[0];
    const int*   segpos   = (const int*)  d_in[1];
    const float* w_q      = (const float*)d_in[7];
    const float* w_kv     = (const float*)d_in[8];
    const float* w_avec   = (const float*)d_in[9];
    const float* q_norm   = (const float*)d_in[10];
    const float* k_norm   = (const float*)d_in[11];
    const float* pre_attn = (const float*)d_in[12];
    const float* post_attn= (const float*)d_in[13];
    const float* pre_ffw  = (const float*)d_in[14];
    const float* post_ffw = (const float*)d_in[15];
    const float* w_gating = (const float*)d_in[16];
    const float* w_linear = (const float*)d_in[17];
    const float* skip     = (const float*)d_in[18];

    float* q    = symaddr<float>(g_q);
    float* kv   = symaddr<float>(g_kv);
    float* aproj= symaddr<float>(g_aproj);
    float* ares = symaddr<float>(g_ares);
    float* fout = symaddr<float>(g_fout);
    bf16* h_hi = symaddr<bf16>(g_h_hi),    *h_lo = symaddr<bf16>(g_h_lo);
    bf16* e_hi = symaddr<bf16>(g_enc_hi),  *e_lo = symaddr<bf16>(g_enc_lo);
    bf16* f_hi = symaddr<bf16>(g_ffin_hi), *f_lo = symaddr<bf16>(g_ffin_lo);
    bf16* a_hi = symaddr<bf16>(g_act_hi),  *a_lo = symaddr<bf16>(g_act_lo);
    bf16* qp_hi = symaddr<bf16>(g_qp_hi),  *qp_lo = symaddr<bf16>(g_qp_lo);
    bf16* kp_hi = symaddr<bf16>(g_kp_hi),  *kp_lo = symaddr<bf16>(g_kp_lo);
    __half* vp  = symaddr<__half>(g_vp);
    bf16* wq_hi = symaddr<bf16>(g_wq_hi),  *wq_lo = symaddr<bf16>(g_wq_lo);
    bf16* wkv_hi= symaddr<bf16>(g_wkv_hi), *wkv_lo= symaddr<bf16>(g_wkv_lo);
    bf16* wav_hi= symaddr<bf16>(g_wav_hi), *wav_lo= symaddr<bf16>(g_wav_lo);
    bf16* wg_hi = symaddr<bf16>(g_wg_hi),  *wg_lo = symaddr<bf16>(g_wg_lo);
    bf16* wl_hi = symaddr<bf16>(g_wl_hi),  *wl_lo = symaddr<bf16>(g_wl_lo);

    cudaFuncSetAttribute(gemm_planes_nt<0>, cudaFuncAttributeMaxDynamicSharedMemorySize, GSM3_TOTAL);
    cudaFuncSetAttribute(gemm_planes_nt<1>, cudaFuncAttributeMaxDynamicSharedMemorySize, GSM3_TOTAL);
    cudaFuncSetAttribute(attn_tc_kernel,    cudaFuncAttributeMaxDynamicSharedMemorySize, ATT_SMEM);

    // 0) weight conversions
    trans_split_kernel<<<dim3(HDIM/32, DMODEL/32, NHEADS), 256>>>(
        w_q, wq_hi, wq_lo, DMODEL, HDIM, (size_t)DMODEL*HDIM, 0, HDIM, DMODEL);
    trans_split_kernel<<<dim3(HDIM/32, DMODEL/32, 2*KVHEADS), 256>>>(
        w_kv, wkv_hi, wkv_lo, DMODEL, HDIM, (size_t)DMODEL*HDIM, 0, HDIM, DMODEL);
    trans_split_kernel<<<dim3(DMODEL/32, (NHEADS*HDIM)/32, 1), 256>>>(
        w_avec, wav_hi, wav_lo, NHEADS*HDIM, DMODEL, 0, 0, 0, NHEADS*HDIM);
    trans_split_kernel<<<dim3(DMODEL/32, FFDIM/32, 1), 256>>>(
        w_linear, wl_hi, wl_lo, FFDIM, DMODEL, 0, 0, 0, FFDIM);
    interleave_split_kernel<<<(2*FFDIM*DMODEL/4 + 255)/256, 256>>>(
        w_gating, wg_hi, wg_lo, 2*FFDIM*DMODEL/4);

    // 1) pre-attn RMSNorm -> h planes
    rows_norm_kernel<<<BT, 256>>>(x, pre_attn, nullptr, nullptr, nullptr, h_hi, h_lo);

    // 2) projections
    gemm_planes_nt<0><<<dim3((NHEADS*HDIM)/128, BT/128), 256, GSM3_TOTAL>>>(
        h_hi, h_lo, wq_hi, wq_lo, q, nullptr, nullptr, DMODEL, NHEADS*HDIM);
    gemm_planes_nt<0><<<dim3((2*KVHEADS*HDIM)/128, BT/128), 256, GSM3_TOTAL>>>(
        h_hi, h_lo, wkv_hi, wkv_lo, kv, nullptr, nullptr, DMODEL, 2*KVHEADS*HDIM);

    // 3) q/k/v norms + rope -> attention planes
    qkv_post_kernel<<<dim3(BT, NHEADS), 256>>>(q, NHEADS*HDIM, q_norm, segpos, 1,
                                               qp_hi, qp_lo, nullptr, NHEADS*HDIM);
    qkv_post_kernel<<<dim3(BT, KVHEADS), 256>>>(kv, 2*KVHEADS*HDIM, k_norm, segpos, 1,
                                                kp_hi, kp_lo, nullptr, KVHEADS*HDIM);
    qkv_post_kernel<<<dim3(BT, KVHEADS), 256>>>(kv + KVHEADS*HDIM, 2*KVHEADS*HDIM,
                                                nullptr, segpos, 0,
                                                nullptr, nullptr, vp, KVHEADS*HDIM);

    // 4) tensor-core attention -> enc planes
    attn_tc_kernel<<<dim3(TSEQ/128, NHEADS, BATCH), 256, ATT_SMEM>>>(
        qp_hi, qp_lo, kp_hi, kp_lo, vp, segpos, e_hi, e_lo);

    // 5) attn output projection
    gemm_planes_nt<0><<<dim3(DMODEL/128, BT/128), 256, GSM3_TOTAL>>>(
        e_hi, e_lo, wav_hi, wav_lo, aproj, nullptr, nullptr, NHEADS*HDIM, DMODEL);

    // 6) post-attn norm + residual
    rows_norm_kernel<<<BT, 256>>>(aproj, post_attn, x, skip, ares, nullptr, nullptr);

    // 7) pre-ffw norm -> ffin planes
    rows_norm_kernel<<<BT, 256>>>(ares, pre_ffw, nullptr, nullptr, nullptr, f_hi, f_lo);

    // 8) gating GEMM with fused gated-GELU epilogue -> act planes
    gemm_planes_nt<1><<<dim3((2*FFDIM)/128, BT/128), 256, GSM3_TOTAL>>>(
        f_hi, f_lo, wg_hi, wg_lo, nullptr, a_hi, a_lo, DMODEL, 2*FFDIM);

    // 9) down projection
    gemm_planes_nt<0><<<dim3(DMODEL/128, BT/128), 256, GSM3_TOTAL>>>(
        a_hi, a_lo, wl_hi, wl_lo, fout, nullptr, nullptr, FFDIM, DMODEL);

    // 10) final: out = ares + rmsnorm(fout, post_ffw)
    rows_norm_kernel<<<BT, 256>>>(fout, post_ffw, ares, nullptr, (float*)d_out,
                                  nullptr, nullptr);
}